// round 13
// baseline (speedup 1.0000x reference)
#include <cuda_runtime.h>
#include <cuda_fp16.h>
#include <cstdint>

#define NN        2048
#define MEM       32
#define HID       256
#define W1S_STRIDE 260   // words; 1040B row, conflict-free fragment gathers

// dynamic smem layout (bytes). 'part' overlays W1s (dead after fragment build).
#define OFF_XF    0                              // 8192
#define OFF_W1S   8192                           // 33280
#define OFF_PART  8192                           // 8192 (overlay)
#define SMEM_TOTAL (8192 + 33280)                // 41472

// precise sigmoid (epilogue only)
__device__ __forceinline__ float sigmoidf_acc(float x) {
    return __fdividef(1.0f, 1.0f + __expf(-x));
}
// fast sigmoid from PRE-HALVED argument: sigma(2*xh) = 0.5*tanh(xh)+0.5
__device__ __forceinline__ float sigmoid_from_half(float xh) {
    float t;
    asm("tanh.approx.f32 %0, %1;" : "=f"(t) : "f"(xh));
    return fmaf(0.5f, t, 0.5f);
}

__device__ __forceinline__ void mma_f16(float c[4],
                                        uint32_t a0, uint32_t a1, uint32_t a2, uint32_t a3,
                                        uint32_t b0, uint32_t b1) {
    asm volatile(
        "mma.sync.aligned.m16n8k16.row.col.f32.f16.f16.f32 "
        "{%0,%1,%2,%3}, {%4,%5,%6,%7}, {%8,%9}, {%0,%1,%2,%3};"
        : "+f"(c[0]), "+f"(c[1]), "+f"(c[2]), "+f"(c[3])
        : "r"(a0), "r"(a1), "r"(a2), "r"(a3), "r"(b0), "r"(b1));
}

// GEMM2 MMA with zero C-init, separate D outputs
__device__ __forceinline__ void mma_f16_zc(float d[4],
                                           uint32_t a0, uint32_t a1, uint32_t a2, uint32_t a3,
                                           uint32_t b0, uint32_t b1) {
    asm volatile(
        "mma.sync.aligned.m16n8k16.row.col.f32.f16.f16.f32 "
        "{%0,%1,%2,%3}, {%4,%5,%6,%7}, {%8,%9}, {%10,%10,%10,%10};"
        : "=f"(d[0]), "=f"(d[1]), "=f"(d[2]), "=f"(d[3])
        : "r"(a0), "r"(a1), "r"(a2), "r"(a3), "r"(b0), "r"(b1), "f"(0.0f));
}

__device__ __forceinline__ uint32_t pack16(float x, float y) {
    half2 h = __floats2half2_rn(x, y);
    return *reinterpret_cast<uint32_t*>(&h);
}

__device__ __forceinline__ void cp16(uint32_t dst, const void* src) {
    asm volatile("cp.async.cg.shared.global [%0], [%1], 16;" :: "r"(dst), "l"(src));
}

__global__ __launch_bounds__(256, 5)
void nlm_kernel(const float* __restrict__ state,   // (128, 2048, 32)
                const float* __restrict__ w1,      // (2048, 32, 256)
                const float* __restrict__ b1,      // (2048, 256)
                const float* __restrict__ w2,      // (2048, 128, 2)
                const float* __restrict__ b2,      // (2048, 2)
                const float* __restrict__ Tg,      // (1,)
                float* __restrict__ out)           // (128, 2048)
{
    extern __shared__ char smem[];
    const uint32_t sbase = (uint32_t)__cvta_generic_to_shared(smem);
    uint32_t* XF   = (uint32_t*)(smem + OFF_XF);
    float*    W1s  = (float*)(smem + OFF_W1S);
    float*    part = (float*)(smem + OFF_PART);   // overlays W1s

    const int n    = blockIdx.x;
    const int tid  = threadIdx.x;
    const int w    = tid >> 5;     // warp 0..7, owns GLU pair-tiles {2w, 2w+1} = hid cols [16w,16w+16)
    const int lane = tid & 31;
    const int q    = lane & 3;
    const int lr   = lane >> 2;

    // ---------------- Prologue ----------------
    // bias loads first (long scoreboard hidden under cp.async wait)
    const int h0 = (2 * w) * 8 + 2 * q;                 // first tile's g-col (even)
    const float2 ba0  = *reinterpret_cast<const float2*>(&b1[n * 256 + h0]);
    const float2 bbr0 = *reinterpret_cast<const float2*>(&b1[n * 256 + 128 + h0]);
    const float2 ba1  = *reinterpret_cast<const float2*>(&b1[n * 256 + h0 + 8]);
    const float2 bbr1 = *reinterpret_cast<const float2*>(&b1[n * 256 + 136 + h0]);

    // W2 fp16 B-fragment (k16 x n8, only n=0,1 real)
    uint32_t w2b0 = 0, w2b1 = 0;
    if (lr < 2) {
        const float* W2g = w2 + n * 256;
        const int k0 = 16 * w + 2 * q;
        w2b0 = pack16(W2g[k0 * 2 + lr],       W2g[(k0 + 1) * 2 + lr]);
        w2b1 = pack16(W2g[(k0 + 8) * 2 + lr], W2g[(k0 + 9) * 2 + lr]);
    }

    const float* W1g = w1 + (size_t)n * (MEM * HID);
    #pragma unroll
    for (int i = 0; i < 8; i++) {
        const int t  = tid + i * 256;
        const int c4 = t & 63;
        const int k  = t >> 6;
        cp16(sbase + OFF_W1S + (k * W1S_STRIDE + 4 * c4) * 4, W1g + k * HID + 4 * c4);
    }
    asm volatile("cp.async.commit_group;");

    // X: 4 x LDG.128 per thread -> fp16 fragments
    const float* Xg = state + (size_t)n * MEM;
    #pragma unroll
    for (int i = 0; i < 4; i++) {
        const int t    = tid + i * 256;
        const int s    = t & 7;          // float4 index in row (k0 = 4s)
        const int brow = t >> 3;         // batch row
        const float4 v = *reinterpret_cast<const float4*>(Xg + (size_t)brow * (NN * MEM) + 4 * s);
        const int p0   = 2 * s;
        const int q0   = p0 & 3;
        const int reg2 = (p0 >> 2) & 1;
        const int ks   = p0 >> 3;
        const int flr  = brow & 7;
        const int reg  = ((brow >> 3) & 1) + 2 * reg2;
        const int m    = brow >> 4;
        const int base = ((m * 2 + ks) * 32 + flr * 4) * 4 + reg;
        XF[base + q0 * 4]       = pack16(v.x, v.y);
        XF[base + (q0 + 1) * 4] = pack16(v.z, v.w);
    }

    // halved gate biases (0.5 folded into gate path; exact power-of-2 scaling)
    const float2 bb0 = make_float2(0.5f * bbr0.x, 0.5f * bbr0.y);
    const float2 bb1 = make_float2(0.5f * bbr1.x, 0.5f * bbr1.y);

    asm volatile("cp.async.wait_group 0;");
    __syncthreads();

    // ---------------- Build W1 fp16 fragments (gate side pre-scaled by 0.5) ----------------
    uint32_t BA[2][2][2], BB[2][2][2];
    #pragma unroll
    for (int p = 0; p < 2; p++) {
        const int colA = (2 * w + p) * 8 + lr;
        const int colB = colA + 128;
        #pragma unroll
        for (int ks = 0; ks < 2; ks++) {
            #pragma unroll
            for (int r = 0; r < 2; r++) {
                const int k = ks * 16 + r * 8 + 2 * q;
                BA[p][ks][r] = pack16(W1s[k * W1S_STRIDE + colA], W1s[(k + 1) * W1S_STRIDE + colA]);
                BB[p][ks][r] = pack16(0.5f * W1s[k * W1S_STRIDE + colB],
                                      0.5f * W1s[(k + 1) * W1S_STRIDE + colB]);
            }
        }
    }
    __syncthreads();   // W1s dead; 'part' (overlay) may now be written

    // ---------------- Mainloop over 8 M-tiles ----------------
    float* myPart = part + w * 256;
    #pragma unroll
    for (int m = 0; m < 8; m++) {
        const uint4 A0 = *reinterpret_cast<const uint4*>(&XF[((m * 2 + 0) * 32 + lane) * 4]);
        const uint4 A1 = *reinterpret_cast<const uint4*>(&XF[((m * 2 + 1) * 32 + lane) * 4]);

        uint32_t Ga0, Ga1, Ga2, Ga3;   // GLU output packed as GEMM2 A-fragment
        {
            float Ca[4] = {ba0.x, ba0.y, ba0.x, ba0.y};
            float Cb[4] = {bb0.x, bb0.y, bb0.x, bb0.y};
            mma_f16(Ca, A0.x, A0.y, A0.z, A0.w, BA[0][0][0], BA[0][0][1]);
            mma_f16(Cb, A0.x, A0.y, A0.z, A0.w, BB[0][0][0], BB[0][0][1]);
            mma_f16(Ca, A1.x, A1.y, A1.z, A1.w, BA[0][1][0], BA[0][1][1]);
            mma_f16(Cb, A1.x, A1.y, A1.z, A1.w, BB[0][1][0], BB[0][1][1]);
            const float g0 = Ca[0] * sigmoid_from_half(Cb[0]);
            const float g1 = Ca[1] * sigmoid_from_half(Cb[1]);
            const float g2 = Ca[2] * sigmoid_from_half(Cb[2]);
            const float g3 = Ca[3] * sigmoid_from_half(Cb[3]);
            Ga0 = pack16(g0, g1);
            Ga1 = pack16(g2, g3);
        }
        {
            float Ca[4] = {ba1.x, ba1.y, ba1.x, ba1.y};
            float Cb[4] = {bb1.x, bb1.y, bb1.x, bb1.y};
            mma_f16(Ca, A0.x, A0.y, A0.z, A0.w, BA[1][0][0], BA[1][0][1]);
            mma_f16(Cb, A0.x, A0.y, A0.z, A0.w, BB[1][0][0], BB[1][0][1]);
            mma_f16(Ca, A1.x, A1.y, A1.z, A1.w, BA[1][1][0], BA[1][1][1]);
            mma_f16(Cb, A1.x, A1.y, A1.z, A1.w, BB[1][1][0], BB[1][1][1]);
            const float g0 = Ca[0] * sigmoid_from_half(Cb[0]);
            const float g1 = Ca[1] * sigmoid_from_half(Cb[1]);
            const float g2 = Ca[2] * sigmoid_from_half(Cb[2]);
            const float g3 = Ca[3] * sigmoid_from_half(Cb[3]);
            Ga2 = pack16(g0, g1);
            Ga3 = pack16(g2, g3);
        }

        // GEMM2 as one MMA: D(16x8) = G(16x16) x W2frag(16x8); cols 0,1 real.
        float d[4];
        mma_f16_zc(d, Ga0, Ga1, Ga2, Ga3, w2b0, w2b1);

        if (q == 0) {
            const int row = m * 16 + lr;
            *reinterpret_cast<float2*>(&myPart[row * 2])       = make_float2(d[0], d[1]);
            *reinterpret_cast<float2*>(&myPart[(row + 8) * 2]) = make_float2(d[2], d[3]);
        }
    }

    __syncthreads();

    // ---------------- Final: sum 8 warp partials (f32x2), GLU2 (precise), /T, store ----------------
    if (tid < 128) {
        uint64_t acc;
        {
            const float2 b2v = *reinterpret_cast<const float2*>(&b2[n * 2]);
            asm("mov.b64 %0, {%1, %2};" : "=l"(acc) : "f"(b2v.x), "f"(b2v.y));
        }
        #pragma unroll
        for (int ww = 0; ww < 8; ww++) {
            const uint64_t pv = *reinterpret_cast<const uint64_t*>(&part[ww * 256 + tid * 2]);
            asm("add.rn.f32x2 %0, %0, %1;" : "+l"(acc) : "l"(pv));
        }
        float y0, y1;
        asm("mov.b64 {%0, %1}, %2;" : "=f"(y0), "=f"(y1) : "l"(acc));
        __stcs(&out[(size_t)tid * NN + n], (y0 * sigmoidf_acc(y1)) / Tg[0]);
    }
}

extern "C" void kernel_launch(void* const* d_in, const int* in_sizes, int n_in,
                              void* d_out, int out_size) {
    const float* state = (const float*)d_in[0];
    const float* w1    = (const float*)d_in[1];
    const float* b1    = (const float*)d_in[2];
    const float* w2    = (const float*)d_in[3];
    const float* b2    = (const float*)d_in[4];
    const float* T     = (const float*)d_in[5];
    float* out = (float*)d_out;
    cudaFuncSetAttribute(nlm_kernel, cudaFuncAttributeMaxDynamicSharedMemorySize, SMEM_TOTAL);
    nlm_kernel<<<NN, 256, SMEM_TOTAL>>>(state, w1, b1, w2, b2, T, out);
}

// round 14
// speedup vs baseline: 1.2778x; 1.2778x over previous
#include <cuda_runtime.h>
#include <cuda_fp16.h>
#include <cstdint>

#define NN        2048
#define MEM       32
#define HID       256
#define W1S_STRIDE 260   // words; 1040B row, conflict-free fragment gathers

// dynamic smem layout (bytes). 'part' overlays W1s (dead after fragment build).
#define OFF_XF    0                              // 8192
#define OFF_W1S   8192                           // 33280
#define OFF_PART  8192                           // 8192 (overlay)
#define SMEM_TOTAL (8192 + 33280)                // 41472

// precise sigmoid (epilogue only)
__device__ __forceinline__ float sigmoidf_acc(float x) {
    return __fdividef(1.0f, 1.0f + __expf(-x));
}

__device__ __forceinline__ void mma_f16(float c[4],
                                        uint32_t a0, uint32_t a1, uint32_t a2, uint32_t a3,
                                        uint32_t b0, uint32_t b1) {
    asm volatile(
        "mma.sync.aligned.m16n8k16.row.col.f32.f16.f16.f32 "
        "{%0,%1,%2,%3}, {%4,%5,%6,%7}, {%8,%9}, {%0,%1,%2,%3};"
        : "+f"(c[0]), "+f"(c[1]), "+f"(c[2]), "+f"(c[3])
        : "r"(a0), "r"(a1), "r"(a2), "r"(a3), "r"(b0), "r"(b1));
}

// GEMM2 MMA with zero C-init, separate D outputs
__device__ __forceinline__ void mma_f16_zc(float d[4],
                                           uint32_t a0, uint32_t a1, uint32_t a2, uint32_t a3,
                                           uint32_t b0, uint32_t b1) {
    asm volatile(
        "mma.sync.aligned.m16n8k16.row.col.f32.f16.f16.f32 "
        "{%0,%1,%2,%3}, {%4,%5,%6,%7}, {%8,%9}, {%10,%10,%10,%10};"
        : "=f"(d[0]), "=f"(d[1]), "=f"(d[2]), "=f"(d[3])
        : "r"(a0), "r"(a1), "r"(a2), "r"(a3), "r"(b0), "r"(b1), "f"(0.0f));
}

__device__ __forceinline__ uint32_t pack16(float x, float y) {
    half2 h = __floats2half2_rn(x, y);
    return *reinterpret_cast<uint32_t*>(&h);
}

// packed GLU: inputs Ca pair (value path, f32) and Cb pair (PRE-HALVED gate, f32);
// returns fp16x2 g = Ca * (0.5*tanh(Cb)+0.5). One MUFU per two values.
__device__ __forceinline__ uint32_t glu_f16x2(float ca0, float ca1, float cb0, float cb1) {
    uint32_t cb = pack16(cb0, cb1);
    uint32_t t;
    asm("tanh.approx.f16x2 %0, %1;" : "=r"(t) : "r"(cb));
    const half2 h05 = __half2half2(__float2half_rn(0.5f));
    half2 sig = __hfma2(*reinterpret_cast<half2*>(&t), h05, h05);
    uint32_t cap = pack16(ca0, ca1);
    half2 g = __hmul2(*reinterpret_cast<half2*>(&cap), sig);
    return *reinterpret_cast<uint32_t*>(&g);
}

__device__ __forceinline__ void cp16(uint32_t dst, const void* src) {
    asm volatile("cp.async.cg.shared.global [%0], [%1], 16;" :: "r"(dst), "l"(src));
}

__global__ __launch_bounds__(256, 4)
void nlm_kernel(const float* __restrict__ state,   // (128, 2048, 32)
                const float* __restrict__ w1,      // (2048, 32, 256)
                const float* __restrict__ b1,      // (2048, 256)
                const float* __restrict__ w2,      // (2048, 128, 2)
                const float* __restrict__ b2,      // (2048, 2)
                const float* __restrict__ Tg,      // (1,)
                float* __restrict__ out)           // (128, 2048)
{
    extern __shared__ char smem[];
    const uint32_t sbase = (uint32_t)__cvta_generic_to_shared(smem);
    uint32_t* XF   = (uint32_t*)(smem + OFF_XF);
    float*    W1s  = (float*)(smem + OFF_W1S);
    float*    part = (float*)(smem + OFF_PART);   // overlays W1s

    const int n    = blockIdx.x;
    const int tid  = threadIdx.x;
    const int w    = tid >> 5;     // warp 0..7, owns GLU pair-tiles {2w, 2w+1}
    const int lane = tid & 31;
    const int q    = lane & 3;
    const int lr   = lane >> 2;

    // ---------------- Prologue ----------------
    const int h0 = (2 * w) * 8 + 2 * q;                 // first tile's g-col (even)
    const float2 ba0  = *reinterpret_cast<const float2*>(&b1[n * 256 + h0]);
    const float2 bbr0 = *reinterpret_cast<const float2*>(&b1[n * 256 + 128 + h0]);
    const float2 ba1  = *reinterpret_cast<const float2*>(&b1[n * 256 + h0 + 8]);
    const float2 bbr1 = *reinterpret_cast<const float2*>(&b1[n * 256 + 136 + h0]);

    // W2 fp16 B-fragment (k16 x n8, only n=0,1 real)
    uint32_t w2b0 = 0, w2b1 = 0;
    if (lr < 2) {
        const float* W2g = w2 + n * 256;
        const int k0 = 16 * w + 2 * q;
        w2b0 = pack16(W2g[k0 * 2 + lr],       W2g[(k0 + 1) * 2 + lr]);
        w2b1 = pack16(W2g[(k0 + 8) * 2 + lr], W2g[(k0 + 9) * 2 + lr]);
    }

    const float* W1g = w1 + (size_t)n * (MEM * HID);
    #pragma unroll
    for (int i = 0; i < 8; i++) {
        const int t  = tid + i * 256;
        const int c4 = t & 63;
        const int k  = t >> 6;
        cp16(sbase + OFF_W1S + (k * W1S_STRIDE + 4 * c4) * 4, W1g + k * HID + 4 * c4);
    }
    asm volatile("cp.async.commit_group;");

    // X: 4 x LDG.128 per thread -> fp16 fragments
    const float* Xg = state + (size_t)n * MEM;
    #pragma unroll
    for (int i = 0; i < 4; i++) {
        const int t    = tid + i * 256;
        const int s    = t & 7;          // float4 index in row (k0 = 4s)
        const int brow = t >> 3;         // batch row
        const float4 v = *reinterpret_cast<const float4*>(Xg + (size_t)brow * (NN * MEM) + 4 * s);
        const int p0   = 2 * s;
        const int q0   = p0 & 3;
        const int reg2 = (p0 >> 2) & 1;
        const int ks   = p0 >> 3;
        const int flr  = brow & 7;
        const int reg  = ((brow >> 3) & 1) + 2 * reg2;
        const int m    = brow >> 4;
        const int base = ((m * 2 + ks) * 32 + flr * 4) * 4 + reg;
        XF[base + q0 * 4]       = pack16(v.x, v.y);
        XF[base + (q0 + 1) * 4] = pack16(v.z, v.w);
    }

    // halved gate biases (0.5 folded into gate path; exact power-of-2 scaling)
    const float2 bb0 = make_float2(0.5f * bbr0.x, 0.5f * bbr0.y);
    const float2 bb1 = make_float2(0.5f * bbr1.x, 0.5f * bbr1.y);

    asm volatile("cp.async.wait_group 0;");
    __syncthreads();

    // ---------------- Build W1 fp16 fragments (gate side pre-scaled by 0.5) ----------------
    uint32_t BA[2][2][2], BB[2][2][2];
    #pragma unroll
    for (int p = 0; p < 2; p++) {
        const int colA = (2 * w + p) * 8 + lr;
        const int colB = colA + 128;
        #pragma unroll
        for (int ks = 0; ks < 2; ks++) {
            #pragma unroll
            for (int r = 0; r < 2; r++) {
                const int k = ks * 16 + r * 8 + 2 * q;
                BA[p][ks][r] = pack16(W1s[k * W1S_STRIDE + colA], W1s[(k + 1) * W1S_STRIDE + colA]);
                BB[p][ks][r] = pack16(0.5f * W1s[k * W1S_STRIDE + colB],
                                      0.5f * W1s[(k + 1) * W1S_STRIDE + colB]);
            }
        }
    }
    __syncthreads();   // W1s dead; 'part' (overlay) may now be written

    // ---------------- Mainloop over 8 M-tiles ----------------
    float* myPart = part + w * 256;
    #pragma unroll
    for (int m = 0; m < 8; m++) {
        const uint4 A0 = *reinterpret_cast<const uint4*>(&XF[((m * 2 + 0) * 32 + lane) * 4]);
        const uint4 A1 = *reinterpret_cast<const uint4*>(&XF[((m * 2 + 1) * 32 + lane) * 4]);

        uint32_t Ga0, Ga1, Ga2, Ga3;   // GLU output packed as GEMM2 A-fragment
        {
            float Ca[4] = {ba0.x, ba0.y, ba0.x, ba0.y};
            float Cb[4] = {bb0.x, bb0.y, bb0.x, bb0.y};
            mma_f16(Ca, A0.x, A0.y, A0.z, A0.w, BA[0][0][0], BA[0][0][1]);
            mma_f16(Cb, A0.x, A0.y, A0.z, A0.w, BB[0][0][0], BB[0][0][1]);
            mma_f16(Ca, A1.x, A1.y, A1.z, A1.w, BA[0][1][0], BA[0][1][1]);
            mma_f16(Cb, A1.x, A1.y, A1.z, A1.w, BB[0][1][0], BB[0][1][1]);
            Ga0 = glu_f16x2(Ca[0], Ca[1], Cb[0], Cb[1]);   // (row lr,   k=2q,2q+1)
            Ga1 = glu_f16x2(Ca[2], Ca[3], Cb[2], Cb[3]);   // (row lr+8, k=2q,2q+1)
        }
        {
            float Ca[4] = {ba1.x, ba1.y, ba1.x, ba1.y};
            float Cb[4] = {bb1.x, bb1.y, bb1.x, bb1.y};
            mma_f16(Ca, A0.x, A0.y, A0.z, A0.w, BA[1][0][0], BA[1][0][1]);
            mma_f16(Cb, A0.x, A0.y, A0.z, A0.w, BB[1][0][0], BB[1][0][1]);
            mma_f16(Ca, A1.x, A1.y, A1.z, A1.w, BA[1][1][0], BA[1][1][1]);
            mma_f16(Cb, A1.x, A1.y, A1.z, A1.w, BB[1][1][0], BB[1][1][1]);
            Ga2 = glu_f16x2(Ca[0], Ca[1], Cb[0], Cb[1]);   // (row lr,   k=8+2q,+1)
            Ga3 = glu_f16x2(Ca[2], Ca[3], Cb[2], Cb[3]);   // (row lr+8, k=8+2q,+1)
        }

        // GEMM2 as one MMA: D(16x8) = G(16x16) x W2frag(16x8); cols 0,1 real.
        float d[4];
        mma_f16_zc(d, Ga0, Ga1, Ga2, Ga3, w2b0, w2b1);

        if (q == 0) {
            const int row = m * 16 + lr;
            *reinterpret_cast<float2*>(&myPart[row * 2])       = make_float2(d[0], d[1]);
            *reinterpret_cast<float2*>(&myPart[(row + 8) * 2]) = make_float2(d[2], d[3]);
        }
    }

    __syncthreads();

    // ---------------- Final: sum 8 warp partials (f32x2), GLU2 (precise), /T, store ----------------
    if (tid < 128) {
        uint64_t acc;
        {
            const float2 b2v = *reinterpret_cast<const float2*>(&b2[n * 2]);
            asm("mov.b64 %0, {%1, %2};" : "=l"(acc) : "f"(b2v.x), "f"(b2v.y));
        }
        #pragma unroll
        for (int ww = 0; ww < 8; ww++) {
            const uint64_t pv = *reinterpret_cast<const uint64_t*>(&part[ww * 256 + tid * 2]);
            asm("add.rn.f32x2 %0, %0, %1;" : "+l"(acc) : "l"(pv));
        }
        float y0, y1;
        asm("mov.b64 {%0, %1}, %2;" : "=f"(y0), "=f"(y1) : "l"(acc));
        __stcs(&out[(size_t)tid * NN + n], (y0 * sigmoidf_acc(y1)) / Tg[0]);
    }
}

extern "C" void kernel_launch(void* const* d_in, const int* in_sizes, int n_in,
                              void* d_out, int out_size) {
    const float* state = (const float*)d_in[0];
    const float* w1    = (const float*)d_in[1];
    const float* b1    = (const float*)d_in[2];
    const float* w2    = (const float*)d_in[3];
    const float* b2    = (const float*)d_in[4];
    const float* T     = (const float*)d_in[5];
    float* out = (float*)d_out;
    cudaFuncSetAttribute(nlm_kernel, cudaFuncAttributeMaxDynamicSharedMemorySize, SMEM_TOTAL);
    nlm_kernel<<<NN, 256, SMEM_TOTAL>>>(state, w1, b1, w2, b2, T, out);
}

// round 15
// speedup vs baseline: 1.2854x; 1.0059x over previous
#include <cuda_runtime.h>
#include <cuda_fp16.h>
#include <cstdint>

#define NN        2048
#define MEM       32
#define HID       256
#define W1S_STRIDE 260   // words; 1040B row, conflict-free fragment gathers

// dynamic smem layout (bytes). 'part' overlays W1s (dead after fragment build).
#define OFF_XF    0                              // 8192
#define OFF_W1S   8192                           // 33280
#define OFF_PART  8192                           // 8192 (overlay)
#define SMEM_TOTAL (8192 + 33280)                // 41472

// precise sigmoid (epilogue only)
__device__ __forceinline__ float sigmoidf_acc(float x) {
    return __fdividef(1.0f, 1.0f + __expf(-x));
}

// accumulate form
__device__ __forceinline__ void mma_f16(float c[4],
                                        uint32_t a0, uint32_t a1, uint32_t a2, uint32_t a3,
                                        uint32_t b0, uint32_t b1) {
    asm volatile(
        "mma.sync.aligned.m16n8k16.row.col.f32.f16.f16.f32 "
        "{%0,%1,%2,%3}, {%4,%5,%6,%7}, {%8,%9}, {%0,%1,%2,%3};"
        : "+f"(c[0]), "+f"(c[1]), "+f"(c[2]), "+f"(c[3])
        : "r"(a0), "r"(a1), "r"(a2), "r"(a3), "r"(b0), "r"(b1));
}

// zero-C form (no accumulator init MOVs)
__device__ __forceinline__ void mma_f16_zc(float d[4],
                                           uint32_t a0, uint32_t a1, uint32_t a2, uint32_t a3,
                                           uint32_t b0, uint32_t b1) {
    asm volatile(
        "mma.sync.aligned.m16n8k16.row.col.f32.f16.f16.f32 "
        "{%0,%1,%2,%3}, {%4,%5,%6,%7}, {%8,%9}, {%10,%10,%10,%10};"
        : "=f"(d[0]), "=f"(d[1]), "=f"(d[2]), "=f"(d[3])
        : "r"(a0), "r"(a1), "r"(a2), "r"(a3), "r"(b0), "r"(b1), "f"(0.0f));
}

__device__ __forceinline__ uint32_t pack16(float x, float y) {
    half2 h = __floats2half2_rn(x, y);
    return *reinterpret_cast<uint32_t*>(&h);
}

// packed GLU with packed fp16 biases:
//   g = (pack(ca)+ba) * (0.5*tanh(pack(cb)+bb) + 0.5)      [gate pre-halved]
__device__ __forceinline__ uint32_t glu_f16x2_b(float ca0, float ca1, float cb0, float cb1,
                                                uint32_t ba, uint32_t bb) {
    uint32_t cb = pack16(cb0, cb1);
    half2 cbh = __hadd2(*reinterpret_cast<half2*>(&cb), *reinterpret_cast<half2*>(&bb));
    uint32_t cbv = *reinterpret_cast<uint32_t*>(&cbh);
    uint32_t t;
    asm("tanh.approx.f16x2 %0, %1;" : "=r"(t) : "r"(cbv));
    const half2 h05 = __half2half2(__float2half_rn(0.5f));
    half2 sig = __hfma2(*reinterpret_cast<half2*>(&t), h05, h05);
    uint32_t cap = pack16(ca0, ca1);
    half2 caph = __hadd2(*reinterpret_cast<half2*>(&cap), *reinterpret_cast<half2*>(&ba));
    half2 g = __hmul2(caph, sig);
    return *reinterpret_cast<uint32_t*>(&g);
}

__device__ __forceinline__ void cp16(uint32_t dst, const void* src) {
    asm volatile("cp.async.cg.shared.global [%0], [%1], 16;" :: "r"(dst), "l"(src));
}

__global__ __launch_bounds__(256, 4)
void nlm_kernel(const float* __restrict__ state,   // (128, 2048, 32)
                const float* __restrict__ w1,      // (2048, 32, 256)
                const float* __restrict__ b1,      // (2048, 256)
                const float* __restrict__ w2,      // (2048, 128, 2)
                const float* __restrict__ b2,      // (2048, 2)
                const float* __restrict__ Tg,      // (1,)
                float* __restrict__ out)           // (128, 2048)
{
    extern __shared__ char smem[];
    const uint32_t sbase = (uint32_t)__cvta_generic_to_shared(smem);
    uint32_t* XF   = (uint32_t*)(smem + OFF_XF);
    float*    W1s  = (float*)(smem + OFF_W1S);
    float*    part = (float*)(smem + OFF_PART);   // overlays W1s

    const int n    = blockIdx.x;
    const int tid  = threadIdx.x;
    const int w    = tid >> 5;     // warp 0..7, owns GLU pair-tiles {2w, 2w+1}
    const int lane = tid & 31;
    const int q    = lane & 3;
    const int lr   = lane >> 2;

    // ---------------- Prologue ----------------
    // W1 -> smem in TWO commit groups (k 0..15, then k 16..31)
    const float* W1g = w1 + (size_t)n * (MEM * HID);
    #pragma unroll
    for (int i = 0; i < 4; i++) {
        const int t  = tid + i * 256;
        const int c4 = t & 63;
        const int k  = t >> 6;           // 0..15
        cp16(sbase + OFF_W1S + (k * W1S_STRIDE + 4 * c4) * 4, W1g + k * HID + 4 * c4);
    }
    asm volatile("cp.async.commit_group;");
    #pragma unroll
    for (int i = 4; i < 8; i++) {
        const int t  = tid + i * 256;
        const int c4 = t & 63;
        const int k  = t >> 6;           // 16..31
        cp16(sbase + OFF_W1S + (k * W1S_STRIDE + 4 * c4) * 4, W1g + k * HID + 4 * c4);
    }
    asm volatile("cp.async.commit_group;");

    // biases (packed fp16; gate pre-halved)
    const int h0 = (2 * w) * 8 + 2 * q;                 // first tile's g-col (even)
    const float2 ba0f  = *reinterpret_cast<const float2*>(&b1[n * 256 + h0]);
    const float2 bbr0  = *reinterpret_cast<const float2*>(&b1[n * 256 + 128 + h0]);
    const float2 ba1f  = *reinterpret_cast<const float2*>(&b1[n * 256 + h0 + 8]);
    const float2 bbr1  = *reinterpret_cast<const float2*>(&b1[n * 256 + 136 + h0]);

    // W2 fp16 B-fragment (k16 x n8, only n=0,1 real)
    uint32_t w2b0 = 0, w2b1 = 0;
    if (lr < 2) {
        const float* W2g = w2 + n * 256;
        const int k0 = 16 * w + 2 * q;
        w2b0 = pack16(W2g[k0 * 2 + lr],       W2g[(k0 + 1) * 2 + lr]);
        w2b1 = pack16(W2g[(k0 + 8) * 2 + lr], W2g[(k0 + 9) * 2 + lr]);
    }

    // X: 4 x LDG.128 per thread -> fp16 fragments
    const float* Xg = state + (size_t)n * MEM;
    #pragma unroll
    for (int i = 0; i < 4; i++) {
        const int t    = tid + i * 256;
        const int s    = t & 7;          // float4 index in row (k0 = 4s)
        const int brow = t >> 3;         // batch row
        const float4 v = *reinterpret_cast<const float4*>(Xg + (size_t)brow * (NN * MEM) + 4 * s);
        const int p0   = 2 * s;
        const int q0   = p0 & 3;
        const int reg2 = (p0 >> 2) & 1;
        const int ks   = p0 >> 3;
        const int flr  = brow & 7;
        const int reg  = ((brow >> 3) & 1) + 2 * reg2;
        const int m    = brow >> 4;
        const int base = ((m * 2 + ks) * 32 + flr * 4) * 4 + reg;
        XF[base + q0 * 4]       = pack16(v.x, v.y);
        XF[base + (q0 + 1) * 4] = pack16(v.z, v.w);
    }

    uint32_t ba0 = pack16(ba0f.x, ba0f.y);
    uint32_t bb0 = pack16(0.5f * bbr0.x, 0.5f * bbr0.y);
    uint32_t ba1 = pack16(ba1f.x, ba1f.y);
    uint32_t bb1 = pack16(0.5f * bbr1.x, 0.5f * bbr1.y);

    // ---------------- Build W1 fp16 fragments (split by k-half) ----------------
    uint32_t BA[2][2][2], BB[2][2][2];
    const int colA0 = (2 * w) * 8 + lr;

    asm volatile("cp.async.wait_group 1;");   // first half (k 0..15) resident
    __syncthreads();
    #pragma unroll
    for (int p = 0; p < 2; p++) {
        const int colA = colA0 + p * 8;
        const int colB = colA + 128;
        #pragma unroll
        for (int r = 0; r < 2; r++) {
            const int k = r * 8 + 2 * q;      // ks = 0
            BA[p][0][r] = pack16(W1s[k * W1S_STRIDE + colA], W1s[(k + 1) * W1S_STRIDE + colA]);
            BB[p][0][r] = pack16(0.5f * W1s[k * W1S_STRIDE + colB],
                                 0.5f * W1s[(k + 1) * W1S_STRIDE + colB]);
        }
    }
    asm volatile("cp.async.wait_group 0;");   // second half (k 16..31) resident
    __syncthreads();
    #pragma unroll
    for (int p = 0; p < 2; p++) {
        const int colA = colA0 + p * 8;
        const int colB = colA + 128;
        #pragma unroll
        for (int r = 0; r < 2; r++) {
            const int k = 16 + r * 8 + 2 * q; // ks = 1
            BA[p][1][r] = pack16(W1s[k * W1S_STRIDE + colA], W1s[(k + 1) * W1S_STRIDE + colA]);
            BB[p][1][r] = pack16(0.5f * W1s[k * W1S_STRIDE + colB],
                                 0.5f * W1s[(k + 1) * W1S_STRIDE + colB]);
        }
    }
    __syncthreads();   // W1s dead; 'part' (overlay) may now be written

    // ---------------- Mainloop over 8 M-tiles ----------------
    float* myPart = part + w * 256;
    #pragma unroll
    for (int m = 0; m < 8; m++) {
        const uint4 A0 = *reinterpret_cast<const uint4*>(&XF[((m * 2 + 0) * 32 + lane) * 4]);
        const uint4 A1 = *reinterpret_cast<const uint4*>(&XF[((m * 2 + 1) * 32 + lane) * 4]);

        uint32_t Ga0, Ga1, Ga2, Ga3;   // GLU output packed as GEMM2 A-fragment
        {
            float Ca[4], Cb[4];
            mma_f16_zc(Ca, A0.x, A0.y, A0.z, A0.w, BA[0][0][0], BA[0][0][1]);
            mma_f16_zc(Cb, A0.x, A0.y, A0.z, A0.w, BB[0][0][0], BB[0][0][1]);
            mma_f16(Ca, A1.x, A1.y, A1.z, A1.w, BA[0][1][0], BA[0][1][1]);
            mma_f16(Cb, A1.x, A1.y, A1.z, A1.w, BB[0][1][0], BB[0][1][1]);
            Ga0 = glu_f16x2_b(Ca[0], Ca[1], Cb[0], Cb[1], ba0, bb0);   // (row lr,   k=2q,2q+1)
            Ga1 = glu_f16x2_b(Ca[2], Ca[3], Cb[2], Cb[3], ba0, bb0);   // (row lr+8, k=2q,2q+1)
        }
        {
            float Ca[4], Cb[4];
            mma_f16_zc(Ca, A0.x, A0.y, A0.z, A0.w, BA[1][0][0], BA[1][0][1]);
            mma_f16_zc(Cb, A0.x, A0.y, A0.z, A0.w, BB[1][0][0], BB[1][0][1]);
            mma_f16(Ca, A1.x, A1.y, A1.z, A1.w, BA[1][1][0], BA[1][1][1]);
            mma_f16(Cb, A1.x, A1.y, A1.z, A1.w, BB[1][1][0], BB[1][1][1]);
            Ga2 = glu_f16x2_b(Ca[0], Ca[1], Cb[0], Cb[1], ba1, bb1);   // (row lr,   k=8+2q,+1)
            Ga3 = glu_f16x2_b(Ca[2], Ca[3], Cb[2], Cb[3], ba1, bb1);   // (row lr+8, k=8+2q,+1)
        }

        // GEMM2 as one MMA: D(16x8) = G(16x16) x W2frag(16x8); cols 0,1 real.
        float d[4];
        mma_f16_zc(d, Ga0, Ga1, Ga2, Ga3, w2b0, w2b1);

        if (q == 0) {
            const int row = m * 16 + lr;
            *reinterpret_cast<float2*>(&myPart[row * 2])       = make_float2(d[0], d[1]);
            *reinterpret_cast<float2*>(&myPart[(row + 8) * 2]) = make_float2(d[2], d[3]);
        }
    }

    __syncthreads();

    // ---------------- Final: sum 8 warp partials (f32x2), GLU2 (precise), /T, store ----------------
    if (tid < 128) {
        uint64_t acc;
        {
            const float2 b2v = *reinterpret_cast<const float2*>(&b2[n * 2]);
            asm("mov.b64 %0, {%1, %2};" : "=l"(acc) : "f"(b2v.x), "f"(b2v.y));
        }
        #pragma unroll
        for (int ww = 0; ww < 8; ww++) {
            const uint64_t pv = *reinterpret_cast<const uint64_t*>(&part[ww * 256 + tid * 2]);
            asm("add.rn.f32x2 %0, %0, %1;" : "+l"(acc) : "l"(pv));
        }
        float y0, y1;
        asm("mov.b64 {%0, %1}, %2;" : "=f"(y0), "=f"(y1) : "l"(acc));
        __stcs(&out[(size_t)tid * NN + n], (y0 * sigmoidf_acc(y1)) / Tg[0]);
    }
}

extern "C" void kernel_launch(void* const* d_in, const int* in_sizes, int n_in,
                              void* d_out, int out_size) {
    const float* state = (const float*)d_in[0];
    const float* w1    = (const float*)d_in[1];
    const float* b1    = (const float*)d_in[2];
    const float* w2    = (const float*)d_in[3];
    const float* b2    = (const float*)d_in[4];
    const float* T     = (const float*)d_in[5];
    float* out = (float*)d_out;
    cudaFuncSetAttribute(nlm_kernel, cudaFuncAttributeMaxDynamicSharedMemorySize, SMEM_TOTAL);
    nlm_kernel<<<NN, 256, SMEM_TOTAL>>>(state, w1, b1, w2, b2, T, out);
}